// round 1
// baseline (speedup 1.0000x reference)
#include <cuda_runtime.h>
#include <stdint.h>

#define BN 64
#define GN 4999
#define PN 50
#define NPAD 8192
#define PW 157   // ceil(4999/32)

__device__ int      d_order[BN * GN];
__device__ float    d_w[BN * GN];
__device__ unsigned d_pbits[PN * PW];
__device__ int      d_psize[PN];

// ---------------------------------------------------------------------------
// Kernel 1: per-sample descending sort (stable, tie-break by ascending index)
// Bitonic sort of packed 64-bit keys in shared memory.
// ---------------------------------------------------------------------------
__global__ void sort_kernel(const float* __restrict__ expr) {
    extern __shared__ unsigned long long keys[];
    const int b   = blockIdx.x;
    const int tid = threadIdx.x;
    const float* row = expr + (size_t)b * GN;

    for (int i = tid; i < NPAD; i += blockDim.x) {
        unsigned long long k;
        if (i < GN) {
            unsigned u = __float_as_uint(row[i]);
            // map float bits -> monotonically ascending unsigned
            u = (u & 0x80000000u) ? ~u : (u | 0x80000000u);
            unsigned dsc = ~u;  // descending expression order
            k = ((unsigned long long)dsc << 32) | (unsigned)i;
        } else {
            k = 0xFFFFFFFFFFFFFFFFull;  // padding sorts to the end
        }
        keys[i] = k;
    }
    __syncthreads();

    for (int k = 2; k <= NPAD; k <<= 1) {
        for (int j = k >> 1; j > 0; j >>= 1) {
            for (int i = tid; i < NPAD; i += blockDim.x) {
                int ixj = i ^ j;
                if (ixj > i) {
                    unsigned long long a = keys[i];
                    unsigned long long c = keys[ixj];
                    bool up = ((i & k) == 0);
                    if ((a > c) == up) { keys[i] = c; keys[ixj] = a; }
                }
            }
            __syncthreads();
        }
    }

    for (int i = tid; i < GN; i += blockDim.x) {
        unsigned long long kk = keys[i];
        int idx = (int)(kk & 0xFFFFFFFFull);
        d_order[b * GN + i] = idx;
        float x = row[idx];
        d_w[b * GN + i] = sqrtf(sqrtf(fabsf(x)));  // |x|^0.25
    }
}

// ---------------------------------------------------------------------------
// Kernel 2: build pathway bitmask + pathway sizes (single block)
// ---------------------------------------------------------------------------
__global__ void pbuild_kernel(const float* __restrict__ pw) {
    const int tid = threadIdx.x;
    for (int t = tid; t < PN * PW; t += blockDim.x) {
        int p  = t / PW;
        int wi = t % PW;
        unsigned bits = 0;
        int gbase = wi * 32;
        #pragma unroll
        for (int q = 0; q < 32; q++) {
            int g = gbase + q;
            if (g < GN && pw[(size_t)p * GN + g] > 0.0f) bits |= (1u << q);
        }
        d_pbits[t] = bits;
    }
    __syncthreads();
    if (tid < PN) {
        int s = 0;
        for (int wi = 0; wi < PW; wi++) s += __popc(d_pbits[tid * PW + wi]);
        d_psize[tid] = s;
    }
}

// ---------------------------------------------------------------------------
// Kernel 3: enrichment scan. One block per sample; one warp per pathway slot.
// running[i] = prefix_sum(delta), delta = hit ? w/S : -1/denom.
// Track signed value at (first) argmax |running|.
// ---------------------------------------------------------------------------
__global__ void es_kernel(float* __restrict__ out) {
    extern __shared__ char smem[];
    int*      s_order = (int*)smem;                 // GN ints
    float*    s_w     = (float*)(s_order + GN);     // GN floats
    unsigned* s_pb    = (unsigned*)(s_w + GN);      // PN*PW words

    const int b   = blockIdx.x;
    const int tid = threadIdx.x;

    for (int i = tid; i < GN; i += blockDim.x) {
        s_order[i] = d_order[b * GN + i];
        s_w[i]     = d_w[b * GN + i];
    }
    for (int i = tid; i < PN * PW; i += blockDim.x) s_pb[i] = d_pbits[i];
    __syncthreads();

    const int wid  = tid >> 5;
    const int lane = tid & 31;
    const int nw   = blockDim.x >> 5;

    for (int p = wid; p < PN; p += nw) {
        const unsigned* pb = s_pb + p * PW;

        // ---- pass 1: S = sum of w over hits ----
        float S = 0.0f;
        for (int i = lane; i < GN; i += 32) {
            int g = s_order[i];
            if ((pb[g >> 5] >> (g & 31)) & 1u) S += s_w[i];
        }
        #pragma unroll
        for (int off = 16; off; off >>= 1) S += __shfl_down_sync(0xffffffffu, S, off);
        S = __shfl_sync(0xffffffffu, S, 0);

        const int   size      = d_psize[p];
        const float denom     = fmaxf((float)(GN - size), 1.0f);
        const float inv_denom = 1.0f / denom;
        const float invS      = (S > 0.0f) ? (1.0f / S) : 1.0f;  // S<=0: w unnormalized

        // ---- pass 2: warp scan of running statistic, track argmax |r| ----
        float carry = 0.0f;
        float best_abs = -1.0f, best_val = 0.0f;
        int   best_idx = 0x7fffffff;
        const int nchunk = (GN + 31) / 32;

        for (int c = 0; c < nchunk; c++) {
            int i = c * 32 + lane;
            bool valid = (i < GN);
            float delta = 0.0f;
            if (valid) {
                int g = s_order[i];
                bool hit = (pb[g >> 5] >> (g & 31)) & 1u;
                delta = hit ? (s_w[i] * invS) : (-inv_denom);
            }
            // inclusive warp scan
            #pragma unroll
            for (int off = 1; off < 32; off <<= 1) {
                float t = __shfl_up_sync(0xffffffffu, delta, off);
                if (lane >= off) delta += t;
            }
            float r = carry + delta;
            if (valid) {
                float ar = fabsf(r);
                if (ar > best_abs) { best_abs = ar; best_val = r; best_idx = i; }
            }
            carry = __shfl_sync(0xffffffffu, r, 31);
        }

        // ---- reduce across lanes: max |r|, tie -> smallest index ----
        #pragma unroll
        for (int off = 16; off; off >>= 1) {
            float oa = __shfl_down_sync(0xffffffffu, best_abs, off);
            float ov = __shfl_down_sync(0xffffffffu, best_val, off);
            int   oi = __shfl_down_sync(0xffffffffu, best_idx, off);
            if (oa > best_abs || (oa == best_abs && oi < best_idx)) {
                best_abs = oa; best_val = ov; best_idx = oi;
            }
        }
        if (lane == 0) out[b * PN + p] = (size > 0) ? best_val : 0.0f;
    }
}

// ---------------------------------------------------------------------------
extern "C" void kernel_launch(void* const* d_in, const int* in_sizes, int n_in,
                              void* d_out, int out_size) {
    const float* expr = (const float*)d_in[0];   // [B, G]
    const float* pw   = (const float*)d_in[1];   // [P, G]
    float* out        = (float*)d_out;           // [B, P]

    const int sort_smem = NPAD * 8;                              // 65536 B
    const int es_smem   = GN * 8 + PN * PW * 4;                  // 71392 B

    cudaFuncSetAttribute(sort_kernel, cudaFuncAttributeMaxDynamicSharedMemorySize, sort_smem);
    cudaFuncSetAttribute(es_kernel,   cudaFuncAttributeMaxDynamicSharedMemorySize, es_smem);

    sort_kernel<<<BN, 1024, sort_smem>>>(expr);
    pbuild_kernel<<<1, 1024>>>(pw);
    es_kernel<<<BN, 512, es_smem>>>(out);
}

// round 2
// speedup vs baseline: 5.4612x; 5.4612x over previous
#include <cuda_runtime.h>
#include <stdint.h>
#include <cub/block/block_radix_sort.cuh>

#define BN 64
#define GN 4999
#define PN 50
#define PW 157            // ceil(4999/32)
#define SEG 157           // ceil(4999/32) positions per lane

__device__ int      d_order[BN * GN];
__device__ float    d_w[BN * GN];
__device__ unsigned d_pbits[PN * PW];
__device__ int      d_psize[PN];

// ---------------------------------------------------------------------------
// Kernel 1: per-sample descending stable sort via cub BlockRadixSort.
// Key = (descending-monotone float bits << 13) | index   (45 significant bits)
// ---------------------------------------------------------------------------
#define SORT_THREADS 512
#define SORT_ITEMS   10   // 5120 slots >= 4999

__global__ void __launch_bounds__(SORT_THREADS, 1)
sort_kernel(const float* __restrict__ expr) {
    typedef cub::BlockRadixSort<unsigned long long, SORT_THREADS, SORT_ITEMS> Sorter;
    __shared__ typename Sorter::TempStorage ts;

    const int b = blockIdx.x;
    const int t = threadIdx.x;
    const float* row = expr + (size_t)b * GN;

    unsigned long long k[SORT_ITEMS];
    #pragma unroll
    for (int j = 0; j < SORT_ITEMS; j++) {
        int i = j * SORT_THREADS + t;            // striped load (coalesced)
        if (i < GN) {
            unsigned u = __float_as_uint(row[i]);
            u = (u & 0x80000000u) ? ~u : (u | 0x80000000u);   // ascending map
            unsigned dsc = ~u;                                 // descending
            k[j] = ((unsigned long long)dsc << 13) | (unsigned)i;
        } else {
            k[j] = 0xFFFFFFFFFFFFFFFFull;
        }
    }

    Sorter(ts).Sort(k, 0, 45);

    #pragma unroll
    for (int j = 0; j < SORT_ITEMS; j++) {
        int pos = t * SORT_ITEMS + j;            // blocked arrangement after sort
        if (pos < GN) {
            int idx = (int)(k[j] & 0x1FFFull);
            unsigned dsc = (unsigned)(k[j] >> 13);
            unsigned u   = ~dsc;
            // invert monotone map, keep |f| bits only
            unsigned absbits = (u & 0x80000000u) ? (u & 0x7FFFFFFFu)
                                                 : ((~u) & 0x7FFFFFFFu);
            float af = __uint_as_float(absbits);
            d_order[b * GN + pos] = idx;
            d_w[b * GN + pos]     = sqrtf(sqrtf(af));   // |x|^0.25
        }
    }
}

// ---------------------------------------------------------------------------
// Kernel 2: pathway bitmask + size. One block per pathway, ballot-based.
// ---------------------------------------------------------------------------
__global__ void pbuild_kernel(const float* __restrict__ pw) {
    const int p    = blockIdx.x;
    const int tid  = threadIdx.x;     // 256
    const int wid  = tid >> 5;
    const int lane = tid & 31;
    __shared__ int wcnt[8];

    int local = 0;
    for (int wi = wid; wi < PW; wi += 8) {
        int g = wi * 32 + lane;
        bool hit = (g < GN) && (pw[(size_t)p * GN + g] > 0.0f);
        unsigned bits = __ballot_sync(0xffffffffu, hit);
        if (lane == 0) d_pbits[p * PW + wi] = bits;
        local += hit ? 1 : 0;
    }
    #pragma unroll
    for (int off = 16; off; off >>= 1) local += __shfl_down_sync(0xffffffffu, local, off);
    if (lane == 0) wcnt[wid] = local;
    __syncthreads();
    if (tid == 0) {
        int s = 0;
        #pragma unroll
        for (int i = 0; i < 8; i++) s += wcnt[i];
        d_psize[p] = s;
    }
}

// ---------------------------------------------------------------------------
// Kernel 3: enrichment. Grid (BN, 2); block caches sample's order/w + all
// pathway bits. One warp per pathway; each lane owns a contiguous segment of
// 157 sorted positions (stride-157 smem access: 157 coprime to 32 => no bank
// conflicts). Two lane-local passes + one warp scan replace the shfl chain.
// ---------------------------------------------------------------------------
__global__ void __launch_bounds__(1024, 1)
es_kernel(float* __restrict__ out) {
    extern __shared__ char smem[];
    int*      s_order = (int*)smem;                 // GN
    float*    s_w     = (float*)(s_order + GN);     // GN
    unsigned* s_pb    = (unsigned*)(s_w + GN);      // PN*PW

    const int b    = blockIdx.x;
    const int half = blockIdx.y;                    // 0: pathways 0-24, 1: 25-49
    const int tid  = threadIdx.x;

    for (int i = tid; i < GN; i += blockDim.x) {
        s_order[i] = d_order[b * GN + i];
        s_w[i]     = d_w[b * GN + i];
    }
    for (int i = tid; i < PN * PW; i += blockDim.x) s_pb[i] = d_pbits[i];
    __syncthreads();

    const int wid  = tid >> 5;
    const int lane = tid & 31;
    const int p    = half * 25 + wid;
    if (wid >= 25) return;

    const unsigned* pb = s_pb + p * PW;
    const int start = lane * SEG;
    const int end   = min(start + SEG, GN);

    // ---- pass A: per-lane hit-weight sum and miss count ----
    float hw = 0.0f;
    int   mc = 0;
    for (int i = start; i < end; i++) {
        int g = s_order[i];
        bool hit = (pb[g >> 5] >> (g & 31)) & 1u;
        if (hit) hw += s_w[i]; else mc++;
    }

    // S = total hit weight across warp
    float S = hw;
    #pragma unroll
    for (int off = 16; off; off >>= 1) S += __shfl_xor_sync(0xffffffffu, S, off);

    const int   size      = d_psize[p];
    const float inv_denom = 1.0f / fmaxf((float)(GN - size), 1.0f);
    const float invS      = (S > 0.0f) ? (1.0f / S) : 1.0f;

    // exclusive prefix of per-lane net delta -> each lane's starting r
    float lane_delta = hw * invS - (float)mc * inv_denom;
    float v = lane_delta;
    #pragma unroll
    for (int off = 1; off < 32; off <<= 1) {
        float t = __shfl_up_sync(0xffffffffu, v, off);
        if (lane >= off) v += t;
    }
    float r = v - lane_delta;   // exclusive prefix

    // ---- pass B: walk segment, track first argmax |r| ----
    float best_abs = -1.0f, best_val = 0.0f;
    int   best_idx = 0x7fffffff;
    for (int i = start; i < end; i++) {
        int g = s_order[i];
        bool hit = (pb[g >> 5] >> (g & 31)) & 1u;
        r += hit ? (s_w[i] * invS) : (-inv_denom);
        float ar = fabsf(r);
        if (ar > best_abs) { best_abs = ar; best_val = r; best_idx = i; }
    }

    // ---- cross-lane argmax reduce (tie -> smallest index) ----
    #pragma unroll
    for (int off = 16; off; off >>= 1) {
        float oa = __shfl_down_sync(0xffffffffu, best_abs, off);
        float ov = __shfl_down_sync(0xffffffffu, best_val, off);
        int   oi = __shfl_down_sync(0xffffffffu, best_idx, off);
        if (oa > best_abs || (oa == best_abs && oi < best_idx)) {
            best_abs = oa; best_val = ov; best_idx = oi;
        }
    }
    if (lane == 0) out[b * PN + p] = (size > 0) ? best_val : 0.0f;
}

// ---------------------------------------------------------------------------
extern "C" void kernel_launch(void* const* d_in, const int* in_sizes, int n_in,
                              void* d_out, int out_size) {
    const float* expr = (const float*)d_in[0];   // [B, G]
    const float* pw   = (const float*)d_in[1];   // [P, G]
    float* out        = (float*)d_out;           // [B, P]

    const int es_smem = GN * 8 + PN * PW * 4;    // 71392 B

    cudaFuncSetAttribute(es_kernel, cudaFuncAttributeMaxDynamicSharedMemorySize, es_smem);

    sort_kernel<<<BN, SORT_THREADS>>>(expr);
    pbuild_kernel<<<PN, 256>>>(pw);
    es_kernel<<<dim3(BN, 2), 1024, es_smem>>>(out);
}